// round 1
// baseline (speedup 1.0000x reference)
#include <cuda_runtime.h>
#include <cstdint>

// Problem constants
#define BB    16
#define CINC  128
#define NF    16     // num_filters n
#define LSZ   32     // spatial
#define CCW   32     // cin / kappa (weight channels)
#define RSTR  37     // smem row stride (conflict-free: 37r+4c8 distinct mod 32)
#define UROWS 34     // rows 0..33 (rows 32,33 = zero pad)
#define USTRIDE (UROWS * RSTR)          // 1258 floats per channel plane
#define WF_U64  (CCW * 9 * 8)           // 2304 weight pairs (u64 each)
#define SMEM_BYTES (WF_U64 * 8 + CCW * USTRIDE * 4)   // 18432 + 161024 = 179456

__device__ __forceinline__ unsigned long long fdup(float x) {
    unsigned long long r; unsigned u = __float_as_uint(x);
    asm("mov.b64 %0, {%1,%2};" : "=l"(r) : "r"(u), "r"(u));
    return r;
}
__device__ __forceinline__ unsigned long long fma2(unsigned long long a,
                                                   unsigned long long b,
                                                   unsigned long long c) {
    unsigned long long d;
    asm("fma.rn.f32x2 %0, %1, %2, %3;" : "=l"(d) : "l"(a), "l"(b), "l"(c));
    return d;
}

__global__ void __launch_bounds__(256, 1)
fconv_kernel(const float* __restrict__ x, const float* __restrict__ w,
             float* __restrict__ out) {
    const int dg  = blockIdx.x;   // d-group 0..8
    const int b   = blockIdx.y;
    const int tid = threadIdx.x;

    extern __shared__ unsigned char smraw[];
    unsigned long long* wf = (unsigned long long*)smraw;          // [cc][t][j][np] pairs (n0,n1)
    float* u = (float*)(smraw + WF_U64 * 8);                      // [32][34][37]

    // ---- zero u (covers spatial zero-padding rows 32,33 and cols >=32) ----
    for (int i = tid; i < CCW * USTRIDE; i += 256) u[i] = 0.0f;

    // ---- build flipped weight pairs: wf[cc][t][j][np] = (w[2np,cc,2-t,2-j], w[2np+1,...]) ----
    for (int p = tid; p < WF_U64; p += 256) {
        int np = p & 7;
        int rem = p >> 3;
        int j  = rem % 3;
        int t  = (rem / 3) % 3;
        int cc = rem / 9;
        int base = cc * 9 + (2 - t) * 3 + (2 - j);
        float w0 = w[(2 * np)     * 288 + base];
        float w1 = w[(2 * np + 1) * 288 + base];
        ((float2*)wf)[p] = make_float2(w0, w1);   // low = even n
    }
    __syncthreads();

    // ---- load u[cc] = 0.5 * ( x[(8dg - cc)%128] + x[(-8dg - cc)%128] ) ----
    {
        const int m = dg * 8;
        for (int k = tid; k < CCW * 256; k += 256) {   // 8192 float4 elements
            int cc = k >> 8;
            int rr = (k >> 3) & 31;
            int c4 = k & 7;
            int ca = (m - cc + 128) & 127;
            int cb = (256 - m - cc) & 127;
            const float4* xa = (const float4*)(x + ((size_t)b * CINC + ca) * 1024) + rr * 8 + c4;
            const float4* xb = (const float4*)(x + ((size_t)b * CINC + cb) * 1024) + rr * 8 + c4;
            float4 va = *xa, vb = *xb;
            float* d = u + cc * USTRIDE + rr * RSTR + c4 * 4;
            d[0] = 0.5f * (va.x + vb.x);
            d[1] = 0.5f * (va.y + vb.y);
            d[2] = 0.5f * (va.z + vb.z);
            d[3] = 0.5f * (va.w + vb.w);
        }
    }
    __syncthreads();

    // ---- main loop: each thread computes 4 spatial cols x 16 n outputs ----
    const int ho = tid >> 3;
    const int wo = (tid & 7) << 2;

    unsigned long long acc[8][4];
#pragma unroll
    for (int a = 0; a < 8; a++)
#pragma unroll
        for (int s = 0; s < 4; s++) acc[a][s] = 0ull;

    const float* ub = u + ho * RSTR + wo;

#pragma unroll 1
    for (int cc = 0; cc < CCW; ++cc) {
        const float* up = ub + cc * USTRIDE;
        const ulonglong2* wp = (const ulonglong2*)(wf + cc * 72);
#pragma unroll
        for (int t = 0; t < 3; t++) {
            unsigned long long xd[6];
#pragma unroll
            for (int q = 0; q < 6; q++) xd[q] = fdup(up[t * RSTR + q]);
#pragma unroll
            for (int j = 0; j < 3; j++) {
                ulonglong2 wA = wp[(t * 3 + j) * 4 + 0];
                ulonglong2 wB = wp[(t * 3 + j) * 4 + 1];
                ulonglong2 wC = wp[(t * 3 + j) * 4 + 2];
                ulonglong2 wD = wp[(t * 3 + j) * 4 + 3];
                unsigned long long wv[8] = {wA.x, wA.y, wB.x, wB.y,
                                            wC.x, wC.y, wD.x, wD.y};
#pragma unroll
                for (int np = 0; np < 8; np++) {
                    acc[np][0] = fma2(wv[np], xd[j + 0], acc[np][0]);
                    acc[np][1] = fma2(wv[np], xd[j + 1], acc[np][1]);
                    acc[np][2] = fma2(wv[np], xd[j + 2], acc[np][2]);
                    acc[np][3] = fma2(wv[np], xd[j + 3], acc[np][3]);
                }
            }
        }
    }

    // ---- epilogue: write d-group dg, duplicate to 16-dg for dg in 1..7 ----
    float* o1 = out + (((size_t)b * 256 + dg * 16)) * 1024 + ho * 32 + wo;
    float* o2 = out + (((size_t)b * 256 + (16 - dg) * 16)) * 1024 + ho * 32 + wo;
    const bool dup = (dg >= 1 && dg <= 7);

#pragma unroll
    for (int np = 0; np < 8; np++) {
        float4 v0, v1;
        v0.x = __uint_as_float((unsigned)acc[np][0]);
        v0.y = __uint_as_float((unsigned)acc[np][1]);
        v0.z = __uint_as_float((unsigned)acc[np][2]);
        v0.w = __uint_as_float((unsigned)acc[np][3]);
        v1.x = __uint_as_float((unsigned)(acc[np][0] >> 32));
        v1.y = __uint_as_float((unsigned)(acc[np][1] >> 32));
        v1.z = __uint_as_float((unsigned)(acc[np][2] >> 32));
        v1.w = __uint_as_float((unsigned)(acc[np][3] >> 32));
        *(float4*)(o1 + (size_t)(2 * np)     * 1024) = v0;
        *(float4*)(o1 + (size_t)(2 * np + 1) * 1024) = v1;
        if (dup) {
            *(float4*)(o2 + (size_t)(2 * np)     * 1024) = v0;
            *(float4*)(o2 + (size_t)(2 * np + 1) * 1024) = v1;
        }
    }
}

extern "C" void kernel_launch(void* const* d_in, const int* in_sizes, int n_in,
                              void* d_out, int out_size) {
    const float* x = (const float*)d_in[0];
    const float* w = (const float*)d_in[1];
    float* out = (float*)d_out;

    cudaFuncSetAttribute(fconv_kernel,
                         cudaFuncAttributeMaxDynamicSharedMemorySize, SMEM_BYTES);

    dim3 grid(9, BB);   // 9 distinct d-groups x 16 batches = 144 CTAs (one wave)
    fconv_kernel<<<grid, 256, SMEM_BYTES>>>(x, w, out);
}